// round 1
// baseline (speedup 1.0000x reference)
#include <cuda_runtime.h>

// LLaDA2 group-limited router, GB300 sm_103a.
// Octet design: 8 lanes per token (lane "sub" owns one 32-expert group),
// 4 tokens per warp. All selection on order-transformed uint32 keys
// (exact fp32 ordering), indices carried as payload.

#define NUM_EXPERTS 256
#define EPG 32          // experts per group
#define NGROUP 8
#define TOPKG 4
#define TOPK 8
#define ROUTER_SCALE 2.5f

// Order-preserving float->uint transform (monotone, total order).
static __device__ __forceinline__ unsigned orderf(float f) {
    unsigned u = __float_as_uint(f);
    unsigned m = ((unsigned)((int)u >> 31)) | 0x80000000u;
    return u ^ m;
}
static __device__ __forceinline__ float unorderf(unsigned k) {
    unsigned m = (~((unsigned)((int)k >> 31))) | 0x80000000u;
    return __uint_as_float(k ^ m);
}

// Compare-exchange, descending (max to first slot), payload follows key.
static __device__ __forceinline__ void ce2(unsigned& ka, unsigned& xa,
                                           unsigned& kb, unsigned& xb) {
    bool t = ka >= kb;
    unsigned kx = t ? ka : kb;
    unsigned kn = t ? kb : ka;
    unsigned ix = t ? xa : xb;
    unsigned in_ = t ? xb : xa;
    ka = kx; kb = kn; xa = ix; xb = in_;
}

// Batcher 8-input sorting network (19 CE), descending.
static __device__ __forceinline__ void sort8_desc(unsigned k[8], unsigned x[8]) {
    ce2(k[0],x[0],k[1],x[1]); ce2(k[2],x[2],k[3],x[3]);
    ce2(k[4],x[4],k[5],x[5]); ce2(k[6],x[6],k[7],x[7]);
    ce2(k[0],x[0],k[2],x[2]); ce2(k[1],x[1],k[3],x[3]);
    ce2(k[4],x[4],k[6],x[6]); ce2(k[5],x[5],k[7],x[7]);
    ce2(k[1],x[1],k[2],x[2]); ce2(k[5],x[5],k[6],x[6]);
    ce2(k[0],x[0],k[4],x[4]); ce2(k[1],x[1],k[5],x[5]);
    ce2(k[2],x[2],k[6],x[6]); ce2(k[3],x[3],k[7],x[7]);
    ce2(k[2],x[2],k[4],x[4]); ce2(k[3],x[3],k[5],x[5]);
    ce2(k[1],x[1],k[2],x[2]); ce2(k[3],x[3],k[4],x[4]); ce2(k[5],x[5],k[6],x[6]);
}

// L (sorted desc) := top-8 of L ∪ C (both sorted desc).
// max(L[i], C[7-i]) is the top-8 multiset and bitonic -> 12-CE bitonic clean.
static __device__ __forceinline__ void merge_top8(unsigned Lk[8], unsigned Li[8],
                                                  const unsigned Ck[8], const unsigned Ci[8]) {
    unsigned tk[8], ti[8];
#pragma unroll
    for (int i = 0; i < 8; ++i) {
        bool t = Lk[i] >= Ck[7 - i];
        tk[i] = t ? Lk[i] : Ck[7 - i];
        ti[i] = t ? Li[i] : Ci[7 - i];
    }
    ce2(tk[0],ti[0],tk[4],ti[4]); ce2(tk[1],ti[1],tk[5],ti[5]);
    ce2(tk[2],ti[2],tk[6],ti[6]); ce2(tk[3],ti[3],tk[7],ti[7]);
    ce2(tk[0],ti[0],tk[2],ti[2]); ce2(tk[1],ti[1],tk[3],ti[3]);
    ce2(tk[4],ti[4],tk[6],ti[6]); ce2(tk[5],ti[5],tk[7],ti[7]);
    ce2(tk[0],ti[0],tk[1],ti[1]); ce2(tk[2],ti[2],tk[3],ti[3]);
    ce2(tk[4],ti[4],tk[5],ti[5]); ce2(tk[6],ti[6],tk[7],ti[7]);
#pragma unroll
    for (int i = 0; i < 8; ++i) { Lk[i] = tk[i]; Li[i] = ti[i]; }
}

static __device__ __forceinline__ float sigmoid_fast(float x) {
    float e = __expf(-x);            // FMUL + MUFU.EX2
    float d = 1.0f + e;
    float r;
    asm("rcp.approx.f32 %0, %1;" : "=f"(r) : "f"(d));  // MUFU.RCP
    return r;
}

__global__ void __launch_bounds__(256)
router_kernel(const float* __restrict__ logits,
              const float* __restrict__ bias,
              float* __restrict__ out_w,
              float* __restrict__ out_i,
              int T) {
    const int warp = threadIdx.x >> 5;
    const int lane = threadIdx.x & 31;
    const int oct  = lane >> 3;   // which token of the warp's 4
    const int sub  = lane & 7;    // group owned by this lane

    int token = blockIdx.x * 32 + warp * 4 + oct;
    const bool valid = token < T;
    const int tok = valid ? token : (T - 1);   // keep all lanes converged

    const float* lp = logits + (size_t)tok * NUM_EXPERTS + sub * EPG;
    const float* bp = bias + sub * EPG;

    // --- Phase 1: per-lane sorted top-8 of its 32 (biased-score keys) ---
    unsigned Lk[8], Li[8];
#pragma unroll
    for (int c = 0; c < 4; ++c) {
        float4 x0 = __ldg((const float4*)(lp + c * 8));
        float4 x1 = __ldg((const float4*)(lp + c * 8 + 4));
        float4 b0 = __ldg((const float4*)(bp + c * 8));
        float4 b1 = __ldg((const float4*)(bp + c * 8 + 4));
        float v[8]  = {x0.x, x0.y, x0.z, x0.w, x1.x, x1.y, x1.z, x1.w};
        float bb[8] = {b0.x, b0.y, b0.z, b0.w, b1.x, b1.y, b1.z, b1.w};
        unsigned Ck[8], Ci[8];
#pragma unroll
        for (int j = 0; j < 8; ++j) {
            float s = sigmoid_fast(v[j]);
            Ck[j] = orderf(s + bb[j]);
            Ci[j] = (unsigned)(sub * EPG + c * 8 + j);   // global expert id
        }
        sort8_desc(Ck, Ci);
        if (c == 0) {
#pragma unroll
            for (int j = 0; j < 8; ++j) { Lk[j] = Ck[j]; Li[j] = Ci[j]; }
        } else {
            merge_top8(Lk, Li, Ck, Ci);
        }
    }

    // --- Phase 2: group score = sum of top-2 biased values (lane-local!) ---
    float gs = unorderf(Lk[0]) + unorderf(Lk[1]);

    // rank of my group among the 8 (strictly-greater, tie -> lower group idx)
    int rank = 0;
#pragma unroll
    for (int g = 1; g < 8; ++g) {
        float og = __shfl_xor_sync(0xffffffffu, gs, g, 8);
        int osub = sub ^ g;
        rank += (og > gs || (og == gs && osub < sub)) ? 1 : 0;
    }
    if (rank >= TOPKG) {   // group masked out: kill all my candidates
#pragma unroll
        for (int j = 0; j < 8; ++j) Lk[j] = 0u;
    }

    // --- Phase 3: extract global top-8 from the 8 per-lane sorted lists ---
    unsigned mykey = 0u, myidx = 0u;
#pragma unroll
    for (int r = 0; r < TOPK; ++r) {
        unsigned hk = Lk[0], hi = Li[0];
#pragma unroll
        for (int m = 1; m < 8; m <<= 1) {
            unsigned ok = __shfl_xor_sync(0xffffffffu, hk, m, 8);
            unsigned oi = __shfl_xor_sync(0xffffffffu, hi, m, 8);
            bool take = (ok > hk) || (ok == hk && oi < hi);
            hk = take ? ok : hk;
            hi = take ? oi : hi;
        }
        if (sub == r) { mykey = hk; myidx = hi; }   // lane r records rank r
        bool win = ((hi >> 5) == (unsigned)sub);    // idx/32 == owning group
#pragma unroll
        for (int j = 0; j < 7; ++j) {               // pop my head if I won
            Lk[j] = win ? Lk[j + 1] : Lk[j];
            Li[j] = win ? Li[j + 1] : Li[j];
        }
        Lk[7] = win ? 0u : Lk[7];
    }

    // --- Phase 4: weights = sigmoid score (biased - bias), renorm, scale ---
    float biased = unorderf(mykey);
    float bv = __ldg(bias + myidx);
    float score = biased - bv;

    float wsum = score;
#pragma unroll
    for (int m = 1; m < 8; m <<= 1)
        wsum += __shfl_xor_sync(0xffffffffu, wsum, m, 8);

    float w = score * __fdividef(ROUTER_SCALE, wsum + 1e-20f);

    if (valid) {
        out_w[(size_t)token * TOPK + sub] = w;
        if (out_i) out_i[(size_t)token * TOPK + sub] = (float)myidx;
    }
}

extern "C" void kernel_launch(void* const* d_in, const int* in_sizes, int n_in,
                              void* d_out, int out_size) {
    // Inputs: router_logits [T,256] f32, expert_bias [256] f32 (order per
    // metadata; identify defensively by size).
    const float* logits = (const float*)d_in[0];
    const float* bias   = (n_in > 1) ? (const float*)d_in[1] : nullptr;
    int s0 = in_sizes[0];
    int s1 = (n_in > 1) ? in_sizes[1] : 0;
    if (s0 == NUM_EXPERTS && s1 > NUM_EXPERTS) {
        const float* t = logits; logits = bias; bias = t;
        int ts = s0; s0 = s1; s1 = ts;
    }
    int T = s0 / NUM_EXPERTS;

    float* out_w = (float*)d_out;
    // Harness concatenates (topk_weights, topk_ids) -> 2*T*8 output elements.
    float* out_i = (out_size >= T * 2 * TOPK) ? (out_w + (size_t)T * TOPK) : nullptr;

    dim3 grid((T + 31) / 32);
    router_kernel<<<grid, 256>>>(logits, bias, out_w, out_i, T);
}

// round 3
// speedup vs baseline: 1.0119x; 1.0119x over previous
#include <cuda_runtime.h>
#include <math_constants.h>

// LLaDA2 group-limited router, GB300 sm_103a — round 3.
// Exact float keys (bit-identical ordering to reference), payload idx carried.
// Compare-exchanges use FMNMX/FSETP on the (idle) fma pipe + 2 SEL on alu,
// cutting the R1 ALU-port bottleneck (71%) roughly in half.

#define NUM_EXPERTS 256
#define EPG 32
#define TOPKG 4
#define TOPK 8
#define ROUTER_SCALE 2.5f

#define NEG_INF (-CUDART_INF_F)

// Compare-exchange, descending; exact float keys, idx payload.
// On ties keeps original order (t=false), idx tiebreak handled in phase 3.
static __device__ __forceinline__ void cef(float& ka, unsigned& xa,
                                           float& kb, unsigned& xb) {
    float kx = fmaxf(ka, kb);       // FMNMX (fma pipe)
    float kn = fminf(ka, kb);       // FMNMX (fma pipe)
    bool t = (kb > ka);             // FSETP (fma pipe)
    unsigned ix = t ? xb : xa;      // SEL (alu)
    unsigned in_ = t ? xa : xb;     // SEL (alu)
    ka = kx; kb = kn; xa = ix; xb = in_;
}

// max-select only (for merge prologue): keep larger of (L, C) in L.
static __device__ __forceinline__ void maxsel(float& lk, unsigned& li,
                                              float ck, unsigned ci) {
    bool t = (ck > lk);
    lk = fmaxf(lk, ck);
    li = t ? ci : li;
}

// Batcher 8-input sorting network (19 CE), descending.
static __device__ __forceinline__ void sort8(float k[8], unsigned x[8]) {
    cef(k[0],x[0],k[1],x[1]); cef(k[2],x[2],k[3],x[3]);
    cef(k[4],x[4],k[5],x[5]); cef(k[6],x[6],k[7],x[7]);
    cef(k[0],x[0],k[2],x[2]); cef(k[1],x[1],k[3],x[3]);
    cef(k[4],x[4],k[6],x[6]); cef(k[5],x[5],k[7],x[7]);
    cef(k[1],x[1],k[2],x[2]); cef(k[5],x[5],k[6],x[6]);
    cef(k[0],x[0],k[4],x[4]); cef(k[1],x[1],k[5],x[5]);
    cef(k[2],x[2],k[6],x[6]); cef(k[3],x[3],k[7],x[7]);
    cef(k[2],x[2],k[4],x[4]); cef(k[3],x[3],k[5],x[5]);
    cef(k[1],x[1],k[2],x[2]); cef(k[3],x[3],k[4],x[4]); cef(k[5],x[5],k[6],x[6]);
}

// L := top-8 of L ∪ C (both sorted desc): 8 max-selects + 12-CE bitonic clean.
static __device__ __forceinline__ void merge8(float Lk[8], unsigned Li[8],
                                              const float Ck[8], const unsigned Ci[8]) {
#pragma unroll
    for (int i = 0; i < 8; ++i) maxsel(Lk[i], Li[i], Ck[7 - i], Ci[7 - i]);
    cef(Lk[0],Li[0],Lk[4],Li[4]); cef(Lk[1],Li[1],Lk[5],Li[5]);
    cef(Lk[2],Li[2],Lk[6],Li[6]); cef(Lk[3],Li[3],Lk[7],Li[7]);
    cef(Lk[0],Li[0],Lk[2],Li[2]); cef(Lk[1],Li[1],Lk[3],Li[3]);
    cef(Lk[4],Li[4],Lk[6],Li[6]); cef(Lk[5],Li[5],Lk[7],Li[7]);
    cef(Lk[0],Li[0],Lk[1],Li[1]); cef(Lk[2],Li[2],Lk[3],Li[3]);
    cef(Lk[4],Li[4],Lk[5],Li[5]); cef(Lk[6],Li[6],Lk[7],Li[7]);
}

static __device__ __forceinline__ float sigmoid_fast(float x) {
    float e = __expf(-x);
    float d = 1.0f + e;
    float r;
    asm("rcp.approx.f32 %0, %1;" : "=f"(r) : "f"(d));
    return r;
}

// Compute sorted top-8 (keys+ids) of one 8-expert chunk.
static __device__ __forceinline__ void load_chunk(const float* lp, const float* bp,
                                                  int base_idx, int c,
                                                  float Ck[8], unsigned Ci[8]) {
    float4 x0 = __ldg((const float4*)(lp + c * 8));
    float4 x1 = __ldg((const float4*)(lp + c * 8 + 4));
    float4 b0 = __ldg((const float4*)(bp + c * 8));
    float4 b1 = __ldg((const float4*)(bp + c * 8 + 4));
    float v[8]  = {x0.x, x0.y, x0.z, x0.w, x1.x, x1.y, x1.z, x1.w};
    float bb[8] = {b0.x, b0.y, b0.z, b0.w, b1.x, b1.y, b1.z, b1.w};
#pragma unroll
    for (int j = 0; j < 8; ++j) {
        Ck[j] = sigmoid_fast(v[j]) + bb[j];      // exact reference rounding
        Ci[j] = (unsigned)(base_idx + c * 8 + j);
    }
    sort8(Ck, Ci);
}

__global__ void __launch_bounds__(256)
router_kernel(const float* __restrict__ logits,
              const float* __restrict__ bias,
              float* __restrict__ out_w,
              float* __restrict__ out_i,
              int T) {
    const int warp = threadIdx.x >> 5;
    const int lane = threadIdx.x & 31;
    const int sub  = lane & 7;          // group owned by this lane
    const int oct  = lane >> 3;         // token slot within warp

    int token = blockIdx.x * 32 + warp * 4 + oct;
    const bool valid = token < T;
    const int tok = valid ? token : (T - 1);

    const float* lp = logits + (size_t)tok * NUM_EXPERTS + sub * EPG;
    const float* bp = bias + sub * EPG;
    const int base_idx = sub * EPG;

    // --- Phase 1: per-lane sorted top-8 of its 32 experts (tree merges) ---
    float Lk[8];  unsigned Li[8];
    {
        float Ak[8], Bk[8]; unsigned Ai[8], Bi[8];
        load_chunk(lp, bp, base_idx, 0, Lk, Li);
        load_chunk(lp, bp, base_idx, 1, Ak, Ai);
        merge8(Lk, Li, Ak, Ai);                     // top8 of chunks 0,1
        load_chunk(lp, bp, base_idx, 2, Bk, Bi);
        load_chunk(lp, bp, base_idx, 3, Ak, Ai);
        merge8(Bk, Bi, Ak, Ai);                     // top8 of chunks 2,3
        merge8(Lk, Li, Bk, Bi);                     // top8 of all 32
    }

    // --- Phase 2: group score = top-2 sum (exact); top-4 groups ---
    float gs = Lk[0] + Lk[1];
    int rank = 0;
#pragma unroll
    for (int g = 1; g < 8; ++g) {
        float og = __shfl_xor_sync(0xffffffffu, gs, g, 8);
        int osub = sub ^ g;
        rank += (og > gs || (og == gs && osub < sub)) ? 1 : 0;
    }
    if (rank >= TOPKG) {
#pragma unroll
        for (int j = 0; j < 8; ++j) Lk[j] = NEG_INF;
    }

    // --- Phase 3: global top-8 across the octet (exact idx tiebreak) ---
    float mykey = 0.0f; unsigned myidx = 0u;
#pragma unroll
    for (int r = 0; r < TOPK; ++r) {
        float hk = Lk[0]; unsigned hi = Li[0];
#pragma unroll
        for (int m = 1; m < 8; m <<= 1) {
            float ok    = __shfl_xor_sync(0xffffffffu, hk, m, 8);
            unsigned oi = __shfl_xor_sync(0xffffffffu, hi, m, 8);
            bool take = (ok > hk) || (ok == hk && oi < hi);
            hk = take ? ok : hk;
            hi = take ? oi : hi;
        }
        if (sub == r) { mykey = hk; myidx = hi; }
        bool win = ((hi >> 5) == (unsigned)sub) && (hi == Li[0]);
#pragma unroll
        for (int j = 0; j < 7 - r; ++j) {
            Lk[j] = win ? Lk[j + 1] : Lk[j];
            Li[j] = win ? Li[j + 1] : Li[j];
        }
        if (r == 0) Lk[7] = win ? NEG_INF : Lk[7];  // deepest slot only reachable once
    }

    // --- Phase 4: weight = sigmoid score, renormalize, scale ---
    float bv = __ldg(bias + myidx);
    float score = mykey - bv;

    float wsum = score;
#pragma unroll
    for (int m = 1; m < 8; m <<= 1)
        wsum += __shfl_xor_sync(0xffffffffu, wsum, m, 8);

    float w = score * __fdividef(ROUTER_SCALE, wsum + 1e-20f);

    if (valid) {
        out_w[(size_t)token * TOPK + sub] = w;
        if (out_i) out_i[(size_t)token * TOPK + sub] = (float)myidx;
    }
}

extern "C" void kernel_launch(void* const* d_in, const int* in_sizes, int n_in,
                              void* d_out, int out_size) {
    const float* logits = (const float*)d_in[0];
    const float* bias   = (n_in > 1) ? (const float*)d_in[1] : nullptr;
    int s0 = in_sizes[0];
    int s1 = (n_in > 1) ? in_sizes[1] : 0;
    if (s0 == NUM_EXPERTS && s1 > NUM_EXPERTS) {
        const float* tp = logits; logits = bias; bias = tp;
        int ts = s0; s0 = s1; s1 = ts;
    }
    int T = s0 / NUM_EXPERTS;

    float* out_w = (float*)d_out;
    float* out_i = (out_size >= T * 2 * TOPK) ? (out_w + (size_t)T * TOPK) : nullptr;

    dim3 grid((T + 31) / 32);
    router_kernel<<<grid, 256>>>(logits, bias, out_w, out_i, T);
}

// round 4
// speedup vs baseline: 1.4041x; 1.3875x over previous
#include <cuda_runtime.h>
#include <math_constants.h>

// LLaDA2 group-limited router, GB300 sm_103a — round 4.
// Coalesced loads + smem key staging (kills the 74% L1 ceiling) and
// group-mask-first: only the 4 surviving groups get the expensive keyed
// top-8 sort, at 2 lanes per group (16 keys each).

#define NUM_EXPERTS 256
#define TOPK 8
#define TOPKG 4
#define ROUTER_SCALE 2.5f
#define NEG_INF (-CUDART_INF_F)

#define GROW 36                 // floats per padded 32-expert group row (144B)
#define TROW (8 * GROW)         // floats per token (8 groups)
#define WROWS (4 * TROW)        // floats per warp (4 tokens)

// ---- keyed compare-exchange (intra-lane sorts; identical to R3) ----
static __device__ __forceinline__ void cef(float& ka, unsigned& xa,
                                           float& kb, unsigned& xb) {
    float kx = fmaxf(ka, kb);
    float kn = fminf(ka, kb);
    bool t = (kb > ka);
    unsigned ix = t ? xb : xa;
    unsigned in_ = t ? xa : xb;
    ka = kx; kb = kn; xa = ix; xb = in_;
}
static __device__ __forceinline__ void maxsel(float& lk, unsigned& li,
                                              float ck, unsigned ci) {
    bool t = (ck > lk);
    lk = fmaxf(lk, ck);
    li = t ? ci : li;
}
// ---- idx-tie-aware CE (exact, symmetric) for the cross-lane pair merge ----
static __device__ __forceinline__ void cet(float& ka, unsigned& xa,
                                           float& kb, unsigned& xb) {
    bool t = (kb > ka) || (kb == ka && xb < xa);
    float nka = t ? kb : ka;
    float nkb = t ? ka : kb;
    unsigned nxa = t ? xb : xa;
    unsigned nxb = t ? xa : xb;
    ka = nka; kb = nkb; xa = nxa; xb = nxb;
}
static __device__ __forceinline__ void maxselt(float& lk, unsigned& li,
                                               float ck, unsigned ci) {
    bool t = (ck > lk) || (ck == lk && ci < li);
    lk = t ? ck : lk;
    li = t ? ci : li;
}

// Batcher 8-input sorting network (19 CE), descending.
static __device__ __forceinline__ void sort8(float k[8], unsigned x[8]) {
    cef(k[0],x[0],k[1],x[1]); cef(k[2],x[2],k[3],x[3]);
    cef(k[4],x[4],k[5],x[5]); cef(k[6],x[6],k[7],x[7]);
    cef(k[0],x[0],k[2],x[2]); cef(k[1],x[1],k[3],x[3]);
    cef(k[4],x[4],k[6],x[6]); cef(k[5],x[5],k[7],x[7]);
    cef(k[1],x[1],k[2],x[2]); cef(k[5],x[5],k[6],x[6]);
    cef(k[0],x[0],k[4],x[4]); cef(k[1],x[1],k[5],x[5]);
    cef(k[2],x[2],k[6],x[6]); cef(k[3],x[3],k[7],x[7]);
    cef(k[2],x[2],k[4],x[4]); cef(k[3],x[3],k[5],x[5]);
    cef(k[1],x[1],k[2],x[2]); cef(k[3],x[3],k[4],x[4]); cef(k[5],x[5],k[6],x[6]);
}

// L := top-8 of L ∪ C (both sorted desc): 8 max-selects + 12-CE bitonic clean.
static __device__ __forceinline__ void merge8(float Lk[8], unsigned Li[8],
                                              const float Ck[8], const unsigned Ci[8]) {
#pragma unroll
    for (int i = 0; i < 8; ++i) maxsel(Lk[i], Li[i], Ck[7 - i], Ci[7 - i]);
    cef(Lk[0],Li[0],Lk[4],Li[4]); cef(Lk[1],Li[1],Lk[5],Li[5]);
    cef(Lk[2],Li[2],Lk[6],Li[6]); cef(Lk[3],Li[3],Lk[7],Li[7]);
    cef(Lk[0],Li[0],Lk[2],Li[2]); cef(Lk[1],Li[1],Lk[3],Li[3]);
    cef(Lk[4],Li[4],Lk[6],Li[6]); cef(Lk[5],Li[5],Lk[7],Li[7]);
    cef(Lk[0],Li[0],Lk[1],Li[1]); cef(Lk[2],Li[2],Lk[3],Li[3]);
    cef(Lk[4],Li[4],Lk[5],Li[5]); cef(Lk[6],Li[6],Lk[7],Li[7]);
}
// Tie-aware variant (used for the symmetric cross-lane pair merge).
static __device__ __forceinline__ void merge8t(float Lk[8], unsigned Li[8],
                                               const float Ck[8], const unsigned Ci[8]) {
#pragma unroll
    for (int i = 0; i < 8; ++i) maxselt(Lk[i], Li[i], Ck[7 - i], Ci[7 - i]);
    cet(Lk[0],Li[0],Lk[4],Li[4]); cet(Lk[1],Li[1],Lk[5],Li[5]);
    cet(Lk[2],Li[2],Lk[6],Li[6]); cet(Lk[3],Li[3],Lk[7],Li[7]);
    cet(Lk[0],Li[0],Lk[2],Li[2]); cet(Lk[1],Li[1],Lk[3],Li[3]);
    cet(Lk[4],Li[4],Lk[6],Li[6]); cet(Lk[5],Li[5],Lk[7],Li[7]);
    cet(Lk[0],Li[0],Lk[1],Li[1]); cet(Lk[2],Li[2],Lk[3],Li[3]);
    cet(Lk[4],Li[4],Lk[5],Li[5]); cet(Lk[6],Li[6],Lk[7],Li[7]);
}

static __device__ __forceinline__ float sigmoid_fast(float x) {
    float e = __expf(-x);
    float d = 1.0f + e;
    float r;
    asm("rcp.approx.f32 %0, %1;" : "=f"(r) : "f"(d));
    return r;
}

__global__ void __launch_bounds__(256)
router_kernel(const float* __restrict__ logits,
              const float* __restrict__ bias,
              float* __restrict__ out_w,
              float* __restrict__ out_i,
              int T) {
    __shared__ float skey[8 * WROWS];   // 36864 B, warp-private regions

    const int warp = threadIdx.x >> 5;
    const int lane = threadIdx.x & 31;
    float* wk = skey + warp * WROWS;

    const int tok0 = blockIdx.x * 32 + warp * 4;

    // Bias for my 8 contiguous experts, loaded once (coalesced, L1-hit).
    float4 bv0 = __ldg((const float4*)(bias + lane * 8));
    float4 bv1 = __ldg((const float4*)(bias + lane * 8 + 4));
    float bb[8] = {bv0.x, bv0.y, bv0.z, bv0.w, bv1.x, bv1.y, bv1.z, bv1.w};

    const int g_mine = lane >> 2;       // my 8 experts belong to this group
    const int q = lane & 3;             // quarter within the group

    // ---- Pass A (coalesced): keys -> smem; exact group top-2 scores ----
    float gs_t[4];
#pragma unroll
    for (int t = 0; t < 4; ++t) {
        int tk = min(tok0 + t, T - 1);
        const float* lp = logits + (size_t)tk * NUM_EXPERTS + lane * 8;
        float4 x0 = __ldg((const float4*)lp);
        float4 x1 = __ldg((const float4*)(lp + 4));
        float v[8] = {x0.x, x0.y, x0.z, x0.w, x1.x, x1.y, x1.z, x1.w};
        float k[8];
#pragma unroll
        for (int j = 0; j < 8; ++j) k[j] = sigmoid_fast(v[j]) + bb[j];

        float* dst = wk + t * TROW + g_mine * GROW + q * 8;
        *(float4*)dst       = make_float4(k[0], k[1], k[2], k[3]);
        *(float4*)(dst + 4) = make_float4(k[4], k[5], k[6], k[7]);

        // lane top-2 (values only; sum is symmetric so no idx needed)
        float m1 = fmaxf(k[0], k[1]);
        float m2 = fminf(k[0], k[1]);
#pragma unroll
        for (int j = 2; j < 8; ++j) {
            m2 = fmaxf(m2, fminf(m1, k[j]));
            m1 = fmaxf(m1, k[j]);
        }
        // quad butterfly: exact top-2 of the group's 32
#pragma unroll
        for (int m = 1; m < 4; m <<= 1) {
            float o1 = __shfl_xor_sync(0xffffffffu, m1, m);
            float o2 = __shfl_xor_sync(0xffffffffu, m2, m);
            float mn = fminf(m1, o1);
            float c  = (m1 >= o1) ? m2 : o2;
            m1 = fmaxf(m1, o1);
            m2 = fmaxf(mn, c);
        }
        gs_t[t] = m1 + m2;
    }
    __syncwarp();

    // ---- Octet phase: lane (oct, sub); token = tok0+oct ----
    const int sub = lane & 7;
    const int oct = lane >> 3;

    // gather gs of (token oct, group sub): quad lane sub*4 holds it
    float g0 = __shfl_sync(0xffffffffu, gs_t[0], sub * 4);
    float g1 = __shfl_sync(0xffffffffu, gs_t[1], sub * 4);
    float g2 = __shfl_sync(0xffffffffu, gs_t[2], sub * 4);
    float g3 = __shfl_sync(0xffffffffu, gs_t[3], sub * 4);
    float gs = (oct == 0) ? g0 : (oct == 1) ? g1 : (oct == 2) ? g2 : g3;

    // rank of my group (exact jax tie-break: lower index wins)
    int rank = 0;
#pragma unroll
    for (int g = 1; g < 8; ++g) {
        float og = __shfl_xor_sync(0xffffffffu, gs, g, 8);
        int osub = sub ^ g;
        rank += (og > gs || (og == gs && osub < sub)) ? 1 : 0;
    }

    // nibble map: nibble r = group with rank r (ranks unique, survivors 0..3)
    unsigned nm = (rank < TOPKG) ? ((unsigned)sub << (rank * 4)) : 0u;
    nm |= __shfl_xor_sync(0xffffffffu, nm, 1, 8);
    nm |= __shfl_xor_sync(0xffffffffu, nm, 2, 8);
    nm |= __shfl_xor_sync(0xffffffffu, nm, 4, 8);
    const int gsel = (nm >> ((sub >> 1) * 4)) & 7;   // my assigned survivor
    const int half = sub & 1;                        // my 16-expert half

    // ---- Pass B: keyed top-8 of my 16 keys (from smem) ----
    const float* src = wk + oct * TROW + gsel * GROW + half * 16;
    float4 a0 = *(const float4*)(src);
    float4 a1 = *(const float4*)(src + 4);
    float4 a2 = *(const float4*)(src + 8);
    float4 a3 = *(const float4*)(src + 12);
    const unsigned ibase = (unsigned)(gsel * 32 + half * 16);

    float Ak[8] = {a0.x, a0.y, a0.z, a0.w, a1.x, a1.y, a1.z, a1.w};
    float Bk[8] = {a2.x, a2.y, a2.z, a2.w, a3.x, a3.y, a3.z, a3.w};
    unsigned Ai[8], Bi[8];
#pragma unroll
    for (int j = 0; j < 8; ++j) { Ai[j] = ibase + j; Bi[j] = ibase + 8 + j; }
    sort8(Ak, Ai);
    sort8(Bk, Bi);
    merge8(Ak, Ai, Bk, Bi);                 // sorted top-8 of my 16

    // pair merge with partner (other half of my group) — tie-aware so both
    // lanes of the pair produce the identical, idx-exact list
#pragma unroll
    for (int j = 0; j < 8; ++j) {
        Bk[j] = __shfl_xor_sync(0xffffffffu, Ak[j], 1);
        Bi[j] = __shfl_xor_sync(0xffffffffu, Ai[j], 1);
    }
    merge8t(Ak, Ai, Bk, Bi);                // sorted top-8 of my group (32)

    // ---- Extraction: global top-8 across the 4 survivor lists ----
    float mykey = 0.0f; unsigned myidx = 0u;
#pragma unroll
    for (int r = 0; r < TOPK; ++r) {
        float hk = Ak[0]; unsigned hi = Ai[0];
#pragma unroll
        for (int m = 2; m < 8; m <<= 1) {   // pairs identical -> skip mask 1
            float ok    = __shfl_xor_sync(0xffffffffu, hk, m, 8);
            unsigned oi = __shfl_xor_sync(0xffffffffu, hi, m, 8);
            bool take = (ok > hk) || (ok == hk && oi < hi);
            hk = take ? ok : hk;
            hi = take ? oi : hi;
        }
        if (sub == r) { mykey = hk; myidx = hi; }
        bool win = (hi == Ai[0]);           // expert ids unique per token
#pragma unroll
        for (int j = 0; j < 7 - r; ++j) {
            Ak[j] = win ? Ak[j + 1] : Ak[j];
            Ai[j] = win ? Ai[j + 1] : Ai[j];
        }
        if (r == 0) Ak[7] = win ? NEG_INF : Ak[7];
    }

    // ---- Phase 4: weight = sigmoid score, renormalize, scale ----
    float bvw = __ldg(bias + myidx);
    float score = mykey - bvw;

    float wsum = score;
#pragma unroll
    for (int m = 1; m < 8; m <<= 1)
        wsum += __shfl_xor_sync(0xffffffffu, wsum, m, 8);

    float w = score * __fdividef(ROUTER_SCALE, wsum + 1e-20f);

    if (tok0 + oct < T) {
        size_t o = (size_t)tok0 * TOPK + lane;   // coalesced: tok0*8 + oct*8 + sub
        out_w[o] = w;
        if (out_i) out_i[o] = (float)myidx;
    }
}

extern "C" void kernel_launch(void* const* d_in, const int* in_sizes, int n_in,
                              void* d_out, int out_size) {
    const float* logits = (const float*)d_in[0];
    const float* bias   = (n_in > 1) ? (const float*)d_in[1] : nullptr;
    int s0 = in_sizes[0];
    int s1 = (n_in > 1) ? in_sizes[1] : 0;
    if (s0 == NUM_EXPERTS && s1 > NUM_EXPERTS) {
        const float* tp = logits; logits = bias; bias = tp;
        int ts = s0; s0 = s1; s1 = ts;
    }
    int T = s0 / NUM_EXPERTS;

    float* out_w = (float*)d_out;
    float* out_i = (out_size >= T * 2 * TOPK) ? (out_w + (size_t)T * TOPK) : nullptr;

    dim3 grid((T + 31) / 32);
    router_kernel<<<grid, 256>>>(logits, bias, out_w, out_i, T);
}

// round 5
// speedup vs baseline: 1.4538x; 1.0354x over previous
#include <cuda_runtime.h>
#include <math_constants.h>

// LLaDA2 group-limited router, GB300 sm_103a — round 5.
// Same algorithm as R4 (coalesced pass A -> smem keys -> group-mask-first
// keyed sort). Change: every compare-exchange forced to FSETP+selp.f32
// (fma pipe) instead of FMNMX (alu pipe) to break the 79% alu ceiling.

#define NUM_EXPERTS 256
#define TOPK 8
#define TOPKG 4
#define ROUTER_SCALE 2.5f
#define NEG_INF (-CUDART_INF_F)

#define GROW 36                 // floats per padded 32-expert group row (144B)
#define TROW (8 * GROW)
#define WROWS (4 * TROW)

// ---- CE, descending, forced FSEL key moves (2 alu + 3 fma) ----
static __device__ __forceinline__ void cef(float& ka, unsigned& xa,
                                           float& kb, unsigned& xb) {
    float nka, nkb; unsigned nxa, nxb;
    asm("{\n\t"
        ".reg .pred p;\n\t"
        "setp.gt.f32 p, %5, %4;\n\t"
        "selp.f32 %0, %5, %4, p;\n\t"
        "selp.f32 %1, %4, %5, p;\n\t"
        "selp.b32 %2, %7, %6, p;\n\t"
        "selp.b32 %3, %6, %7, p;\n\t"
        "}"
        : "=f"(nka), "=f"(nkb), "=r"(nxa), "=r"(nxb)
        : "f"(ka), "f"(kb), "r"(xa), "r"(xb));
    ka = nka; kb = nkb; xa = nxa; xb = nxb;
}
static __device__ __forceinline__ void maxsel(float& lk, unsigned& li,
                                              float ck, unsigned ci) {
    float nk; unsigned ni;
    asm("{\n\t"
        ".reg .pred p;\n\t"
        "setp.gt.f32 p, %4, %2;\n\t"
        "selp.f32 %0, %4, %2, p;\n\t"
        "selp.b32 %1, %5, %3, p;\n\t"
        "}"
        : "=f"(nk), "=r"(ni)
        : "f"(lk), "r"(li), "f"(ck), "r"(ci));
    lk = nk; li = ni;
}
// ---- tie-aware CE: (kb>ka) || (kb==ka && xb<xa), symmetric/exact ----
static __device__ __forceinline__ void cet(float& ka, unsigned& xa,
                                           float& kb, unsigned& xb) {
    float nka, nkb; unsigned nxa, nxb;
    asm("{\n\t"
        ".reg .pred p;\n\t"
        "setp.lt.u32 p, %7, %6;\n\t"
        "setp.eq.and.f32 p, %5, %4, p;\n\t"
        "setp.gt.or.f32 p, %5, %4, p;\n\t"
        "selp.f32 %0, %5, %4, p;\n\t"
        "selp.f32 %1, %4, %5, p;\n\t"
        "selp.b32 %2, %7, %6, p;\n\t"
        "selp.b32 %3, %6, %7, p;\n\t"
        "}"
        : "=f"(nka), "=f"(nkb), "=r"(nxa), "=r"(nxb)
        : "f"(ka), "f"(kb), "r"(xa), "r"(xb));
    ka = nka; kb = nkb; xa = nxa; xb = nxb;
}
static __device__ __forceinline__ void maxselt(float& lk, unsigned& li,
                                               float ck, unsigned ci) {
    float nk; unsigned ni;
    asm("{\n\t"
        ".reg .pred p;\n\t"
        "setp.lt.u32 p, %5, %3;\n\t"
        "setp.eq.and.f32 p, %4, %2, p;\n\t"
        "setp.gt.or.f32 p, %4, %2, p;\n\t"
        "selp.f32 %0, %4, %2, p;\n\t"
        "selp.b32 %1, %5, %3, p;\n\t"
        "}"
        : "=f"(nk), "=r"(ni)
        : "f"(lk), "r"(li), "f"(ck), "r"(ci));
    lk = nk; li = ni;
}
// extraction head update: take = (ok>hk)||(ok==hk&&oi<hi)
static __device__ __forceinline__ void takemax(float& hk, unsigned& hi,
                                               float ok, unsigned oi) {
    float nk; unsigned ni;
    asm("{\n\t"
        ".reg .pred p;\n\t"
        "setp.lt.u32 p, %5, %3;\n\t"
        "setp.eq.and.f32 p, %4, %2, p;\n\t"
        "setp.gt.or.f32 p, %4, %2, p;\n\t"
        "selp.f32 %0, %4, %2, p;\n\t"
        "selp.b32 %1, %5, %3, p;\n\t"
        "}"
        : "=f"(nk), "=r"(ni)
        : "f"(hk), "r"(hi), "f"(ok), "r"(oi));
    hk = nk; hi = ni;
}

// Batcher 8-input sorting network (19 CE), descending.
static __device__ __forceinline__ void sort8(float k[8], unsigned x[8]) {
    cef(k[0],x[0],k[1],x[1]); cef(k[2],x[2],k[3],x[3]);
    cef(k[4],x[4],k[5],x[5]); cef(k[6],x[6],k[7],x[7]);
    cef(k[0],x[0],k[2],x[2]); cef(k[1],x[1],k[3],x[3]);
    cef(k[4],x[4],k[6],x[6]); cef(k[5],x[5],k[7],x[7]);
    cef(k[1],x[1],k[2],x[2]); cef(k[5],x[5],k[6],x[6]);
    cef(k[0],x[0],k[4],x[4]); cef(k[1],x[1],k[5],x[5]);
    cef(k[2],x[2],k[6],x[6]); cef(k[3],x[3],k[7],x[7]);
    cef(k[2],x[2],k[4],x[4]); cef(k[3],x[3],k[5],x[5]);
    cef(k[1],x[1],k[2],x[2]); cef(k[3],x[3],k[4],x[4]); cef(k[5],x[5],k[6],x[6]);
}
// L := top-8 of L ∪ C (both sorted desc).
static __device__ __forceinline__ void merge8(float Lk[8], unsigned Li[8],
                                              const float Ck[8], const unsigned Ci[8]) {
#pragma unroll
    for (int i = 0; i < 8; ++i) maxsel(Lk[i], Li[i], Ck[7 - i], Ci[7 - i]);
    cef(Lk[0],Li[0],Lk[4],Li[4]); cef(Lk[1],Li[1],Lk[5],Li[5]);
    cef(Lk[2],Li[2],Lk[6],Li[6]); cef(Lk[3],Li[3],Lk[7],Li[7]);
    cef(Lk[0],Li[0],Lk[2],Li[2]); cef(Lk[1],Li[1],Lk[3],Li[3]);
    cef(Lk[4],Li[4],Lk[6],Li[6]); cef(Lk[5],Li[5],Lk[7],Li[7]);
    cef(Lk[0],Li[0],Lk[1],Li[1]); cef(Lk[2],Li[2],Lk[3],Li[3]);
    cef(Lk[4],Li[4],Lk[5],Li[5]); cef(Lk[6],Li[6],Lk[7],Li[7]);
}
static __device__ __forceinline__ void merge8t(float Lk[8], unsigned Li[8],
                                               const float Ck[8], const unsigned Ci[8]) {
#pragma unroll
    for (int i = 0; i < 8; ++i) maxselt(Lk[i], Li[i], Ck[7 - i], Ci[7 - i]);
    cet(Lk[0],Li[0],Lk[4],Li[4]); cet(Lk[1],Li[1],Lk[5],Li[5]);
    cet(Lk[2],Li[2],Lk[6],Li[6]); cet(Lk[3],Li[3],Lk[7],Li[7]);
    cet(Lk[0],Li[0],Lk[2],Li[2]); cet(Lk[1],Li[1],Lk[3],Li[3]);
    cet(Lk[4],Li[4],Lk[6],Li[6]); cet(Lk[5],Li[5],Lk[7],Li[7]);
    cet(Lk[0],Li[0],Lk[1],Li[1]); cet(Lk[2],Li[2],Lk[3],Li[3]);
    cet(Lk[4],Li[4],Lk[5],Li[5]); cet(Lk[6],Li[6],Lk[7],Li[7]);
}

static __device__ __forceinline__ float sigmoid_fast(float x) {
    float e = __expf(-x);
    float d = 1.0f + e;
    float r;
    asm("rcp.approx.f32 %0, %1;" : "=f"(r) : "f"(d));
    return r;
}

__global__ void __launch_bounds__(256)
router_kernel(const float* __restrict__ logits,
              const float* __restrict__ bias,
              float* __restrict__ out_w,
              float* __restrict__ out_i,
              int T) {
    __shared__ float skey[8 * WROWS];

    const int warp = threadIdx.x >> 5;
    const int lane = threadIdx.x & 31;
    float* wk = skey + warp * WROWS;

    const int tok0 = blockIdx.x * 32 + warp * 4;

    float4 bv0 = __ldg((const float4*)(bias + lane * 8));
    float4 bv1 = __ldg((const float4*)(bias + lane * 8 + 4));
    float bb[8] = {bv0.x, bv0.y, bv0.z, bv0.w, bv1.x, bv1.y, bv1.z, bv1.w};

    const int g_mine = lane >> 2;
    const int q = lane & 3;

    // ---- Pass A (coalesced): keys -> smem; exact group top-2 scores ----
    // (min/max chains intentionally left as FMNMX: keeps alu/fma balanced)
    float gs_t[4];
#pragma unroll
    for (int t = 0; t < 4; ++t) {
        int tk = min(tok0 + t, T - 1);
        const float* lp = logits + (size_t)tk * NUM_EXPERTS + lane * 8;
        float4 x0 = __ldg((const float4*)lp);
        float4 x1 = __ldg((const float4*)(lp + 4));
        float v[8] = {x0.x, x0.y, x0.z, x0.w, x1.x, x1.y, x1.z, x1.w};
        float k[8];
#pragma unroll
        for (int j = 0; j < 8; ++j) k[j] = sigmoid_fast(v[j]) + bb[j];

        float* dst = wk + t * TROW + g_mine * GROW + q * 8;
        *(float4*)dst       = make_float4(k[0], k[1], k[2], k[3]);
        *(float4*)(dst + 4) = make_float4(k[4], k[5], k[6], k[7]);

        float m1 = fmaxf(k[0], k[1]);
        float m2 = fminf(k[0], k[1]);
#pragma unroll
        for (int j = 2; j < 8; ++j) {
            m2 = fmaxf(m2, fminf(m1, k[j]));
            m1 = fmaxf(m1, k[j]);
        }
#pragma unroll
        for (int m = 1; m < 4; m <<= 1) {
            float o1 = __shfl_xor_sync(0xffffffffu, m1, m);
            float o2 = __shfl_xor_sync(0xffffffffu, m2, m);
            float mn = fminf(m1, o1);
            float c  = (m1 >= o1) ? m2 : o2;
            m1 = fmaxf(m1, o1);
            m2 = fmaxf(mn, c);
        }
        gs_t[t] = m1 + m2;
    }
    __syncwarp();

    // ---- Octet phase ----
    const int sub = lane & 7;
    const int oct = lane >> 3;

    float g0 = __shfl_sync(0xffffffffu, gs_t[0], sub * 4);
    float g1 = __shfl_sync(0xffffffffu, gs_t[1], sub * 4);
    float g2 = __shfl_sync(0xffffffffu, gs_t[2], sub * 4);
    float g3 = __shfl_sync(0xffffffffu, gs_t[3], sub * 4);
    float gs = (oct == 0) ? g0 : (oct == 1) ? g1 : (oct == 2) ? g2 : g3;

    int rank = 0;
#pragma unroll
    for (int g = 1; g < 8; ++g) {
        float og = __shfl_xor_sync(0xffffffffu, gs, g, 8);
        int osub = sub ^ g;
        rank += (og > gs || (og == gs && osub < sub)) ? 1 : 0;
    }

    unsigned nm = (rank < TOPKG) ? ((unsigned)sub << (rank * 4)) : 0u;
    nm |= __shfl_xor_sync(0xffffffffu, nm, 1, 8);
    nm |= __shfl_xor_sync(0xffffffffu, nm, 2, 8);
    nm |= __shfl_xor_sync(0xffffffffu, nm, 4, 8);
    const int gsel = (nm >> ((sub >> 1) * 4)) & 7;
    const int half = sub & 1;

    // ---- Pass B: keyed top-8 of my 16 keys ----
    const float* src = wk + oct * TROW + gsel * GROW + half * 16;
    float4 a0 = *(const float4*)(src);
    float4 a1 = *(const float4*)(src + 4);
    float4 a2 = *(const float4*)(src + 8);
    float4 a3 = *(const float4*)(src + 12);
    const unsigned ibase = (unsigned)(gsel * 32 + half * 16);

    float Ak[8] = {a0.x, a0.y, a0.z, a0.w, a1.x, a1.y, a1.z, a1.w};
    float Bk[8] = {a2.x, a2.y, a2.z, a2.w, a3.x, a3.y, a3.z, a3.w};
    unsigned Ai[8], Bi[8];
#pragma unroll
    for (int j = 0; j < 8; ++j) { Ai[j] = ibase + j; Bi[j] = ibase + 8 + j; }
    sort8(Ak, Ai);
    sort8(Bk, Bi);
    merge8(Ak, Ai, Bk, Bi);

#pragma unroll
    for (int j = 0; j < 8; ++j) {
        Bk[j] = __shfl_xor_sync(0xffffffffu, Ak[j], 1);
        Bi[j] = __shfl_xor_sync(0xffffffffu, Ai[j], 1);
    }
    merge8t(Ak, Ai, Bk, Bi);

    // ---- Extraction: global top-8 across the 4 survivor lists ----
    float mykey = 0.0f; unsigned myidx = 0u;
#pragma unroll
    for (int r = 0; r < TOPK; ++r) {
        float hk = Ak[0]; unsigned hi = Ai[0];
#pragma unroll
        for (int m = 2; m < 8; m <<= 1) {
            float ok    = __shfl_xor_sync(0xffffffffu, hk, m, 8);
            unsigned oi = __shfl_xor_sync(0xffffffffu, hi, m, 8);
            takemax(hk, hi, ok, oi);
        }
        if (sub == r) { mykey = hk; myidx = hi; }
        bool win = (hi == Ai[0]);
#pragma unroll
        for (int j = 0; j < 7 - r; ++j) {
            Ak[j] = win ? Ak[j + 1] : Ak[j];
            Ai[j] = win ? Ai[j + 1] : Ai[j];
        }
        if (r == 0) Ak[7] = win ? NEG_INF : Ak[7];
    }

    // ---- Phase 4 ----
    float bvw = __ldg(bias + myidx);
    float score = mykey - bvw;

    float wsum = score;
#pragma unroll
    for (int m = 1; m < 8; m <<= 1)
        wsum += __shfl_xor_sync(0xffffffffu, wsum, m, 8);

    float w = score * __fdividef(ROUTER_SCALE, wsum + 1e-20f);

    if (tok0 + oct < T) {
        size_t o = (size_t)tok0 * TOPK + lane;
        out_w[o] = w;
        if (out_i) out_i[o] = (float)myidx;
    }
}

extern "C" void kernel_launch(void* const* d_in, const int* in_sizes, int n_in,
                              void* d_out, int out_size) {
    const float* logits = (const float*)d_in[0];
    const float* bias   = (n_in > 1) ? (const float*)d_in[1] : nullptr;
    int s0 = in_sizes[0];
    int s1 = (n_in > 1) ? in_sizes[1] : 0;
    if (s0 == NUM_EXPERTS && s1 > NUM_EXPERTS) {
        const float* tp = logits; logits = bias; bias = tp;
        int ts = s0; s0 = s1; s1 = ts;
    }
    int T = s0 / NUM_EXPERTS;

    float* out_w = (float*)d_out;
    float* out_i = (out_size >= T * 2 * TOPK) ? (out_w + (size_t)T * TOPK) : nullptr;

    dim3 grid((T + 31) / 32);
    router_kernel<<<grid, 256>>>(logits, bias, out_w, out_i, T);
}

// round 7
// speedup vs baseline: 1.4750x; 1.0146x over previous
#include <cuda_runtime.h>
#include <math_constants.h>

// LLaDA2 group-limited router, GB300 sm_103a — round 7.
// R5 scalar kernel minus the tie-aware pair merge: extraction now runs over
// the 8 distinct per-lane 16-key lists (3-step tie-aware butterfly, masks
// 1/2/4), saving ~95 alu warp-instrs per warp. 128-thread blocks.

#define NUM_EXPERTS 256
#define TOPK 8
#define TOPKG 4
#define ROUTER_SCALE 2.5f
#define NEG_INF (-CUDART_INF_F)

#define GROW 36                 // floats per padded 32-expert group row (144B)
#define TROW (8 * GROW)
#define WROWS (4 * TROW)
#define NWARPS 4                // 128 threads per block

// ---- scalar keyed CE (descending); ties keep first arg ----
static __device__ __forceinline__ void cef(float& ka, unsigned& xa,
                                           float& kb, unsigned& xb) {
    float kx = fmaxf(ka, kb);
    float kn = fminf(ka, kb);
    bool t = (kb > ka);
    unsigned ix = t ? xb : xa;
    unsigned in_ = t ? xa : xb;
    ka = kx; kb = kn; xa = ix; xb = in_;
}
static __device__ __forceinline__ void maxsel(float& lk, unsigned& li,
                                              float ck, unsigned ci) {
    bool t = (ck > lk);
    lk = fmaxf(lk, ck);
    li = t ? ci : li;
}

// Batcher 8-input sorting network (19 CE), descending.
static __device__ __forceinline__ void sort8(float k[8], unsigned x[8]) {
    cef(k[0],x[0],k[1],x[1]); cef(k[2],x[2],k[3],x[3]);
    cef(k[4],x[4],k[5],x[5]); cef(k[6],x[6],k[7],x[7]);
    cef(k[0],x[0],k[2],x[2]); cef(k[1],x[1],k[3],x[3]);
    cef(k[4],x[4],k[6],x[6]); cef(k[5],x[5],k[7],x[7]);
    cef(k[1],x[1],k[2],x[2]); cef(k[5],x[5],k[6],x[6]);
    cef(k[0],x[0],k[4],x[4]); cef(k[1],x[1],k[5],x[5]);
    cef(k[2],x[2],k[6],x[6]); cef(k[3],x[3],k[7],x[7]);
    cef(k[2],x[2],k[4],x[4]); cef(k[3],x[3],k[5],x[5]);
    cef(k[1],x[1],k[2],x[2]); cef(k[3],x[3],k[4],x[4]); cef(k[5],x[5],k[6],x[6]);
}

// L := top-8 of L ∪ C (both sorted desc): 8 max-selects + 12-CE bitonic clean.
static __device__ __forceinline__ void merge8(float Lk[8], unsigned Li[8],
                                              const float Ck[8], const unsigned Ci[8]) {
#pragma unroll
    for (int i = 0; i < 8; ++i) maxsel(Lk[i], Li[i], Ck[7 - i], Ci[7 - i]);
    cef(Lk[0],Li[0],Lk[4],Li[4]); cef(Lk[1],Li[1],Lk[5],Li[5]);
    cef(Lk[2],Li[2],Lk[6],Li[6]); cef(Lk[3],Li[3],Lk[7],Li[7]);
    cef(Lk[0],Li[0],Lk[2],Li[2]); cef(Lk[1],Li[1],Lk[3],Li[3]);
    cef(Lk[4],Li[4],Lk[6],Li[6]); cef(Lk[5],Li[5],Lk[7],Li[7]);
    cef(Lk[0],Li[0],Lk[1],Li[1]); cef(Lk[2],Li[2],Lk[3],Li[3]);
    cef(Lk[4],Li[4],Lk[5],Li[5]); cef(Lk[6],Li[6],Lk[7],Li[7]);
}

static __device__ __forceinline__ float sigmoid_fast(float x) {
    float e = __expf(-x);
    float d = 1.0f + e;
    float r;
    asm("rcp.approx.f32 %0, %1;" : "=f"(r) : "f"(d));
    return r;
}

__global__ void __launch_bounds__(128)
router_kernel(const float* __restrict__ logits,
              const float* __restrict__ bias,
              float* __restrict__ out_w,
              float* __restrict__ out_i,
              int T) {
    __shared__ float skey[NWARPS * WROWS];   // 18432 B

    const int warp = threadIdx.x >> 5;
    const int lane = threadIdx.x & 31;
    float* wk = skey + warp * WROWS;

    const int tok0 = blockIdx.x * (NWARPS * 4) + warp * 4;

    float4 bv0 = __ldg((const float4*)(bias + lane * 8));
    float4 bv1 = __ldg((const float4*)(bias + lane * 8 + 4));
    float bb[8] = {bv0.x, bv0.y, bv0.z, bv0.w, bv1.x, bv1.y, bv1.z, bv1.w};

    const int g_mine = lane >> 2;
    const int q = lane & 3;

    // ---- Pass A (coalesced): keys -> smem; exact group top-2 scores ----
    float gs_t[4];
#pragma unroll
    for (int t = 0; t < 4; ++t) {
        int tk = min(tok0 + t, T - 1);
        const float* lp = logits + (size_t)tk * NUM_EXPERTS + lane * 8;
        float4 x0 = __ldg((const float4*)lp);
        float4 x1 = __ldg((const float4*)(lp + 4));
        float v[8] = {x0.x, x0.y, x0.z, x0.w, x1.x, x1.y, x1.z, x1.w};
        float k[8];
#pragma unroll
        for (int j = 0; j < 8; ++j) k[j] = sigmoid_fast(v[j]) + bb[j];

        float* dst = wk + t * TROW + g_mine * GROW + q * 8;
        *(float4*)dst       = make_float4(k[0], k[1], k[2], k[3]);
        *(float4*)(dst + 4) = make_float4(k[4], k[5], k[6], k[7]);

        float m1 = fmaxf(k[0], k[1]);
        float m2 = fminf(k[0], k[1]);
#pragma unroll
        for (int j = 2; j < 8; ++j) {
            m2 = fmaxf(m2, fminf(m1, k[j]));
            m1 = fmaxf(m1, k[j]);
        }
#pragma unroll
        for (int m = 1; m < 4; m <<= 1) {
            float o1 = __shfl_xor_sync(0xffffffffu, m1, m);
            float o2 = __shfl_xor_sync(0xffffffffu, m2, m);
            float mn = fminf(m1, o1);
            float c  = (m1 >= o1) ? m2 : o2;
            m1 = fmaxf(m1, o1);
            m2 = fmaxf(mn, c);
        }
        gs_t[t] = m1 + m2;
    }
    __syncwarp();

    // ---- Octet phase ----
    const int sub = lane & 7;
    const int oct = lane >> 3;

    float g0 = __shfl_sync(0xffffffffu, gs_t[0], sub * 4);
    float g1 = __shfl_sync(0xffffffffu, gs_t[1], sub * 4);
    float g2 = __shfl_sync(0xffffffffu, gs_t[2], sub * 4);
    float g3 = __shfl_sync(0xffffffffu, gs_t[3], sub * 4);
    float gs = (oct == 0) ? g0 : (oct == 1) ? g1 : (oct == 2) ? g2 : g3;

    int rank = 0;
#pragma unroll
    for (int g = 1; g < 8; ++g) {
        float og = __shfl_xor_sync(0xffffffffu, gs, g, 8);
        int osub = sub ^ g;
        rank += (og > gs || (og == gs && osub < sub)) ? 1 : 0;
    }

    unsigned nm = (rank < TOPKG) ? ((unsigned)sub << (rank * 4)) : 0u;
    nm |= __shfl_xor_sync(0xffffffffu, nm, 1, 8);
    nm |= __shfl_xor_sync(0xffffffffu, nm, 2, 8);
    nm |= __shfl_xor_sync(0xffffffffu, nm, 4, 8);
    const int gsel = (nm >> ((sub >> 1) * 4)) & 7;
    const int half = sub & 1;

    // ---- Pass B: keyed top-8 of my 16 keys (distinct per lane) ----
    const float* src = wk + oct * TROW + gsel * GROW + half * 16;
    float4 a0 = *(const float4*)(src);
    float4 a1 = *(const float4*)(src + 4);
    float4 a2 = *(const float4*)(src + 8);
    float4 a3 = *(const float4*)(src + 12);
    const unsigned ibase = (unsigned)(gsel * 32 + half * 16);

    float Ak[8] = {a0.x, a0.y, a0.z, a0.w, a1.x, a1.y, a1.z, a1.w};
    float Bk[8] = {a2.x, a2.y, a2.z, a2.w, a3.x, a3.y, a3.z, a3.w};
    unsigned Ai[8], Bi[8];
#pragma unroll
    for (int j = 0; j < 8; ++j) { Ai[j] = ibase + j; Bi[j] = ibase + 8 + j; }
    sort8(Ak, Ai);
    sort8(Bk, Bi);
    merge8(Ak, Ai, Bk, Bi);                 // sorted top-8 of my 16

    // ---- Extraction: global top-8 across 8 distinct lists (masks 1,2,4) ----
    float mykey = 0.0f; unsigned myidx = 0u;
#pragma unroll
    for (int r = 0; r < TOPK; ++r) {
        float hk = Ak[0]; unsigned hi = Ai[0];
#pragma unroll
        for (int m = 1; m < 8; m <<= 1) {
            float ok    = __shfl_xor_sync(0xffffffffu, hk, m, 8);
            unsigned oi = __shfl_xor_sync(0xffffffffu, hi, m, 8);
            bool take = (ok > hk) || (ok == hk && oi < hi);
            hk = take ? ok : hk;
            hi = take ? oi : hi;
        }
        if (sub == r) { mykey = hk; myidx = hi; }
        bool win = (hi == Ai[0]);           // ids unique -> exactly one lane
#pragma unroll
        for (int j = 0; j < 7 - r; ++j) {
            Ak[j] = win ? Ak[j + 1] : Ak[j];
            Ai[j] = win ? Ai[j + 1] : Ai[j];
        }
        if (r == 0) Ak[7] = win ? NEG_INF : Ak[7];
    }

    // ---- Phase 4: weight = sigmoid score, renormalize, scale ----
    float bvw = __ldg(bias + myidx);
    float score = mykey - bvw;

    float wsum = score;
#pragma unroll
    for (int m = 1; m < 8; m <<= 1)
        wsum += __shfl_xor_sync(0xffffffffu, wsum, m, 8);

    float w = score * __fdividef(ROUTER_SCALE, wsum + 1e-20f);

    if (tok0 + oct < T) {
        size_t o = (size_t)tok0 * TOPK + lane;
        out_w[o] = w;
        if (out_i) out_i[o] = (float)myidx;
    }
}

extern "C" void kernel_launch(void* const* d_in, const int* in_sizes, int n_in,
                              void* d_out, int out_size) {
    const float* logits = (const float*)d_in[0];
    const float* bias   = (n_in > 1) ? (const float*)d_in[1] : nullptr;
    int s0 = in_sizes[0];
    int s1 = (n_in > 1) ? in_sizes[1] : 0;
    if (s0 == NUM_EXPERTS && s1 > NUM_EXPERTS) {
        const float* tp = logits; logits = bias; bias = tp;
        int ts = s0; s0 = s1; s1 = ts;
    }
    int T = s0 / NUM_EXPERTS;

    float* out_w = (float*)d_out;
    float* out_i = (out_size >= T * 2 * TOPK) ? (out_w + (size_t)T * TOPK) : nullptr;

    int tokens_per_block = NWARPS * 4;
    dim3 grid((T + tokens_per_block - 1) / tokens_per_block);
    router_kernel<<<grid, NWARPS * 32>>>(logits, bias, out_w, out_i, T);
}